// round 15
// baseline (speedup 1.0000x reference)
#include <cuda_runtime.h>
#include <cuda_bf16.h>
#include <math.h>
#include <stdint.h>

// ---------------- problem constants ----------------
constexpr int B = 4, S = 1024, D = 512, M = 64, H = 8, WIN = 128;
constexpr int T = M + S;            // 1088
constexpr int BT = B * T;           // 4352
constexpr int BS_ = B * S;          // 4096
constexpr int HD = D / H;           // 64
constexpr float LR = 1e-3f, WD = 1e-2f, MAX_ALR = 0.1f, EPS = 1e-8f;
constexpr size_t BTD = (size_t)BT * D;
constexpr size_t BSD = (size_t)BS_ * D;
constexpr int DD = D * D;
constexpr int SPLK = 8;             // 4352/8 = 544 = 17*32

typedef __nv_bfloat16 bf16;

// ---------------- scratch (static device globals; no allocation) ----------------
__device__ float g_xm[BTD];
__device__ float g_pj[3 * BTD];     // fused q,k,v f32
__device__ float g_w[BT];
__device__ float g_z1[BTD];
__device__ float g_h1[BTD];
__device__ float g_g2[BTD];
__device__ float g_dz2[BTD];
__device__ float g_dz1[BTD];
__device__ float g_gW[2 * DD];
__device__ float g_gb[2 * D];
__device__ float g_Wu[2 * DD];
__device__ float g_bu[2 * D];
__device__ float g_r1[BTD];
__device__ float g_qkv[3 * BTD];
__device__ float g_part[SPLK * DD];
__device__ float g_part2[SPLK * DD];
__device__ float g_bqkv[3 * D];
// bf16 hi/lo activations (row-major [rows][k])
__device__ bf16 g_xm_h[BTD], g_xm_l[BTD];
__device__ bf16 g_pj_h[3 * BTD], g_pj_l[3 * BTD];
__device__ bf16 g_h1_h[BTD], g_h1_l[BTD];
__device__ bf16 g_dz2_h[BTD], g_dz2_l[BTD];
__device__ bf16 g_r1_h[BTD], g_r1_l[BTD];
__device__ bf16 g_r_h[BTD], g_r_l[BTD];
__device__ bf16 g_o_h[BSD], g_o_l[BSD];
// bf16 transposed activations [D][BT]
__device__ bf16 g_kT_h[BTD], g_kT_l[BTD];
__device__ bf16 g_h1T_h[BTD], g_h1T_l[BTD];
__device__ bf16 g_dz2T_h[BTD], g_dz2T_l[BTD];
__device__ bf16 g_dz1T_h[BTD], g_dz1T_l[BTD];
// bf16 weights: transposed [out][in] slots 0..8 = Wq,Wk,Wv,W1,W2,swa0..3
__device__ bf16 g_wT_h[9 * DD], g_wT_l[9 * DD];
__device__ bf16 g_w2o_h[DD], g_w2o_l[DD];
__device__ bf16 g_wuT_h[2 * DD], g_wuT_l[2 * DD];

// ---------------- helpers ----------------
__device__ __forceinline__ void bsplit(float f, bf16& h, bf16& l) {
    h = __float2bfloat16(f);
    l = __float2bfloat16(f - __bfloat162float(h));
}

__device__ __forceinline__ void mma_bf16(float* d, const uint32_t* a, const uint32_t* b) {
    asm volatile(
        "mma.sync.aligned.m16n8k16.row.col.f32.bf16.bf16.f32 "
        "{%0,%1,%2,%3}, {%4,%5,%6,%7}, {%8,%9}, {%0,%1,%2,%3};"
        : "+f"(d[0]), "+f"(d[1]), "+f"(d[2]), "+f"(d[3])
        : "r"(a[0]), "r"(a[1]), "r"(a[2]), "r"(a[3]), "r"(b[0]), "r"(b[1]));
}

__device__ __forceinline__ void ldsm_x4(uint32_t& r0, uint32_t& r1, uint32_t& r2,
                                        uint32_t& r3, uint32_t addr) {
    asm volatile("ldmatrix.sync.aligned.m8n8.x4.shared.b16 {%0,%1,%2,%3}, [%4];"
                 : "=r"(r0), "=r"(r1), "=r"(r2), "=r"(r3) : "r"(addr));
}

__device__ __forceinline__ void cp_async16(uint32_t sa, const void* gptr) {
    asm volatile("cp.async.cg.shared.global [%0], [%1], 16;" :: "r"(sa), "l"(gptr));
}
__device__ __forceinline__ void cp_commit() { asm volatile("cp.async.commit_group;"); }
template <int N>
__device__ __forceinline__ void cp_wait() { asm volatile("cp.async.wait_group %0;" :: "n"(N)); }

__device__ __forceinline__ float silu_grad(float z) {
    float sig = 1.f / (1.f + __expf(-z));
    return sig * (1.f + z * (1.f - sig));
}

// ---------------- bf16x3 GEMM, 64x128 tile, BK=32, 3-stage ----------------
// EPI: 0 bias; 1 none; 2 res+silu; 3 lmm2+grad_out fused; 4 dh1+dz1 fused
#define EPI_BIAS 0
#define EPI_NONE 1
#define EPI_RESSILU 2
#define EPI_GRADOUT 3
#define EPI_DZ1 4

constexpr int ROWB = 80;
constexpr int TILE_A = 64 * ROWB;
constexpr int TILE_Bt = 128 * ROWB;
constexpr int AOFF_L = TILE_A;
constexpr int BOFF_H = 2 * TILE_A;
constexpr int BOFF_L = 2 * TILE_A + TILE_Bt;
constexpr int STAGE_B = 2 * TILE_A + 2 * TILE_Bt;  // 30720 B
constexpr int NSTG = 3;
constexpr int GSMEM = NSTG * STAGE_B;              // 92160 B (2 CTAs/SM)

template <int EPI, int ZMODE>  // ZMODE: 0 none; 1 split-K z; 2 batched weights z
__global__ __launch_bounds__(256, 2) void gemm_bf16x3(
    const bf16* __restrict__ Ah, const bf16* __restrict__ Al,
    const bf16* __restrict__ Bh, const bf16* __restrict__ Bl,
    const float* __restrict__ bias, const float* __restrict__ R,
    float* __restrict__ Cf, bf16* __restrict__ Ch, bf16* __restrict__ Cl,
    float* __restrict__ Zf,
    const float* __restrict__ P1, const float* __restrict__ P2, float* __restrict__ O2,
    int Md, int Nd, int Kd) {
    extern __shared__ char smem[];
    const uint32_t sbase = (uint32_t)__cvta_generic_to_shared(smem);

    const int n0 = blockIdx.x * 128;
    const int m0 = blockIdx.y * 64;
    const int tid = threadIdx.x;
    const int warp = tid >> 5, lane = tid & 31;
    const int wm = warp >> 2, wn = warp & 3;
    const int gid = lane >> 2, tig = lane & 3;

    if (ZMODE == 2) {
        size_t wo = (size_t)blockIdx.z * Kd * Nd;
        size_t co = (size_t)blockIdx.z * Md * Nd;
        Bh += wo; Bl += wo;
        bias += (size_t)blockIdx.z * Nd;
        Cf += co;
        if (Ch) { Ch += co; Cl += co; }
    }
    int kbeg = 0, kend = Kd;
    if (ZMODE == 1) {
        int chunk = Kd / SPLK;
        kbeg = blockIdx.z * chunk;
        kend = kbeg + chunk;
        Cf += (size_t)blockIdx.z * Md * Nd;
    }
    const int nIter = (kend - kbeg) / 32;

    float acc[2][4][4];
#pragma unroll
    for (int i = 0; i < 2; i++)
#pragma unroll
        for (int j = 0; j < 4; j++)
#pragma unroll
            for (int c = 0; c < 4; c++) acc[i][j][c] = 0.f;

    uint32_t aterm[2], bterm[2];
#pragma unroll
    for (int im = 0; im < 2; im++)
        aterm[im] = (uint32_t)((wm * 32 + im * 16 + ((lane >> 3) & 1) * 8 + (lane & 7)) * ROWB
                               + ((lane >> 4) & 1) * 16);
#pragma unroll
    for (int p = 0; p < 2; p++)
        bterm[p] = (uint32_t)((wn * 32 + p * 16 + ((lane >> 4) & 1) * 8 + (lane & 7)) * ROWB
                               + ((lane >> 3) & 1) * 16);

    const int lrow = tid >> 2, lc = tid & 3;
    auto loadStage = [&](int k0, int st) {
        uint32_t s0 = sbase + st * STAGE_B;
        uint32_t da = s0 + lrow * ROWB + lc * 16;
        const size_t ga = (size_t)(m0 + lrow) * Kd + k0 + lc * 8;
        cp_async16(da, Ah + ga);
        cp_async16(da + AOFF_L, Al + ga);
        const size_t gb0 = (size_t)(n0 + lrow) * Kd + k0 + lc * 8;
        const size_t gb1 = (size_t)(n0 + lrow + 64) * Kd + k0 + lc * 8;
        uint32_t db0 = s0 + BOFF_H + lrow * ROWB + lc * 16;
        uint32_t db1 = db0 + 64 * ROWB;
        cp_async16(db0, Bh + gb0);
        cp_async16(db1, Bh + gb1);
        cp_async16(db0 + TILE_Bt, Bl + gb0);
        cp_async16(db1 + TILE_Bt, Bl + gb1);
        cp_commit();
    };

    loadStage(kbeg, 0);
    loadStage(kbeg + 32, 1);

    for (int it = 0; it < nIter; it++) {
        if (nIter - 1 - it >= 1) cp_wait<1>();
        else cp_wait<0>();
        __syncthreads();

        int wt = it + NSTG - 1;
        if (wt < nIter) loadStage(kbeg + wt * 32, wt % NSTG);

        const uint32_t so = sbase + (it % NSTG) * STAGE_B;

#pragma unroll
        for (int s = 0; s < 2; s++) {
            const uint32_t ks = s * 32;
            uint32_t ah[2][4], al[2][4];
#pragma unroll
            for (int im = 0; im < 2; im++) {
                ldsm_x4(ah[im][0], ah[im][1], ah[im][2], ah[im][3], so + aterm[im] + ks);
                ldsm_x4(al[im][0], al[im][1], al[im][2], al[im][3],
                        so + AOFF_L + aterm[im] + ks);
            }
            uint32_t bh[4][2], bl[4][2];
#pragma unroll
            for (int p = 0; p < 2; p++) {
                ldsm_x4(bh[2 * p][0], bh[2 * p][1], bh[2 * p + 1][0], bh[2 * p + 1][1],
                        so + BOFF_H + bterm[p] + ks);
                ldsm_x4(bl[2 * p][0], bl[2 * p][1], bl[2 * p + 1][0], bl[2 * p + 1][1],
                        so + BOFF_L + bterm[p] + ks);
            }
#pragma unroll
            for (int im = 0; im < 2; im++)
#pragma unroll
                for (int jn = 0; jn < 4; jn++) {
                    mma_bf16(acc[im][jn], ah[im], bh[jn]);
                    mma_bf16(acc[im][jn], ah[im], bl[jn]);
                    mma_bf16(acc[im][jn], al[im], bh[jn]);
                }
        }
    }

    // ---- epilogue ----
#pragma unroll
    for (int im = 0; im < 2; im++) {
#pragma unroll
        for (int jn = 0; jn < 4; jn++) {
            int col = n0 + wn * 32 + jn * 8 + tig * 2;
#pragma unroll
            for (int rr = 0; rr < 2; rr++) {
                int r_ = m0 + wm * 32 + im * 16 + gid + rr * 8;
                float v0 = acc[im][jn][rr * 2 + 0];
                float v1 = acc[im][jn][rr * 2 + 1];
                if (EPI == EPI_BIAS || EPI == EPI_RESSILU || EPI == EPI_GRADOUT) {
                    v0 += bias[col];
                    v1 += bias[col + 1];
                }
                size_t off = (size_t)r_ * Nd + col;
                if (EPI == EPI_RESSILU) {
                    if (Zf) { Zf[off] = v0; Zf[off + 1] = v1; }
                    float s0 = 1.f / (1.f + __expf(-v0));
                    float s1 = 1.f / (1.f + __expf(-v1));
                    v0 = R[off] + v0 * s0;
                    v1 = R[off + 1] + v1 * s1;
                } else if (EPI == EPI_GRADOUT) {
                    // v = z2; preds = R + silu(z2); g = w[row]*(2/D)*(preds - v_in)
                    float s0 = 1.f / (1.f + __expf(-v0));
                    float s1 = 1.f / (1.f + __expf(-v1));
                    float p0 = R[off] + v0 * s0;
                    float p1 = R[off + 1] + v1 * s1;
                    float wr = P2[r_] * (2.0f / (float)D);
                    float ga0 = wr * (p0 - P1[off]);
                    float ga1 = wr * (p1 - P1[off + 1]);
                    O2[off] = ga0;
                    O2[off + 1] = ga1;
                    v0 = ga0 * silu_grad(v0);
                    v1 = ga1 * silu_grad(v1);
                } else if (EPI == EPI_DZ1) {
                    v0 = (P1[off] + v0) * silu_grad(P2[off]);
                    v1 = (P1[off + 1] + v1) * silu_grad(P2[off + 1]);
                }
                if (Cf) { Cf[off] = v0; Cf[off + 1] = v1; }
                if (Ch) {
                    bf16 h0, l0, h1, l1;
                    bsplit(v0, h0, l0);
                    bsplit(v1, h1, l1);
                    Ch[off] = h0; Ch[off + 1] = h1;
                    Cl[off] = l0; Cl[off + 1] = l1;
                }
            }
        }
    }
}

// ---------------- split-K reduce ----------------
__global__ void reduce_part_kernel(const float* __restrict__ part, float* __restrict__ out, int n) {
    int i = blockIdx.x * 256 + threadIdx.x;
    if (i >= n) return;
    float s = 0.f;
#pragma unroll
    for (int z = 0; z < SPLK; z++) s += part[(size_t)z * n + i];
    out[i] = s;
}

// ---------------- weight split (transposed + W2 original), z = zbase + blockIdx.z ----------------
__global__ void wsplitT_kernel(const float* __restrict__ Wq, const float* __restrict__ Wk,
                               const float* __restrict__ Wv, const float* __restrict__ W1,
                               const float* __restrict__ W2, const float* __restrict__ swa,
                               int zbase) {
    __shared__ float t[32][33];
    int z = zbase + blockIdx.z;
    const float* src = (z == 0) ? Wq : (z == 1) ? Wk : (z == 2) ? Wv : (z == 3) ? W1
                     : (z == 4 || z == 9) ? W2 : swa + (size_t)(z - 5) * DD;
    int c0 = blockIdx.x * 32, r0 = blockIdx.y * 32;
    int tx = threadIdx.x, ty = threadIdx.y;
#pragma unroll
    for (int kk = 0; kk < 4; kk++)
        t[ty + 8 * kk][tx] = src[(size_t)(r0 + ty + 8 * kk) * D + c0 + tx];
    __syncthreads();
    if (z < 9) {
        bf16* dh = g_wT_h + (size_t)z * DD;
        bf16* dl = g_wT_l + (size_t)z * DD;
#pragma unroll
        for (int kk = 0; kk < 4; kk++) {
            float v = t[tx][ty + 8 * kk];
            bf16 h, l;
            bsplit(v, h, l);
            size_t o = (size_t)(c0 + ty + 8 * kk) * D + r0 + tx;
            dh[o] = h; dl[o] = l;
        }
    } else {
#pragma unroll
        for (int kk = 0; kk < 4; kk++) {
            float v = t[ty + 8 * kk][tx];
            bf16 h, l;
            bsplit(v, h, l);
            size_t o = (size_t)(r0 + ty + 8 * kk) * D + c0 + tx;
            g_w2o_h[o] = h; g_w2o_l[o] = l;
        }
    }
}

__global__ void wuT_kernel(const float* __restrict__ Wu) {
    __shared__ float t[32][33];
    int z = blockIdx.z;
    const float* src = Wu + (size_t)z * DD;
    bf16* dh = g_wuT_h + (size_t)z * DD;
    bf16* dl = g_wuT_l + (size_t)z * DD;
    int c0 = blockIdx.x * 32, r0 = blockIdx.y * 32;
    int tx = threadIdx.x, ty = threadIdx.y;
#pragma unroll
    for (int kk = 0; kk < 4; kk++)
        t[ty + 8 * kk][tx] = src[(size_t)(r0 + ty + 8 * kk) * D + c0 + tx];
    __syncthreads();
#pragma unroll
    for (int kk = 0; kk < 4; kk++) {
        float v = t[tx][ty + 8 * kk];
        bf16 h, l;
        bsplit(v, h, l);
        size_t o = (size_t)(c0 + ty + 8 * kk) * D + r0 + tx;
        dh[o] = h; dl[o] = l;
    }
}

// activation transpose-split: src f32 [BT][D] -> dst bf16 hi/lo [D][BT]
__global__ void actT_kernel(const float* __restrict__ src, bf16* __restrict__ dh,
                            bf16* __restrict__ dl) {
    __shared__ float t[32][33];
    int c0 = blockIdx.x * 32;
    int r0 = blockIdx.y * 32;
    int tx = threadIdx.x, ty = threadIdx.y;
#pragma unroll
    for (int kk = 0; kk < 4; kk++)
        t[ty + 8 * kk][tx] = src[(size_t)(r0 + ty + 8 * kk) * D + c0 + tx];
    __syncthreads();
#pragma unroll
    for (int kk = 0; kk < 4; kk++) {
        float v = t[tx][ty + 8 * kk];
        bf16 h, l;
        bsplit(v, h, l);
        size_t o = (size_t)(c0 + ty + 8 * kk) * BT + r0 + tx;
        dh[o] = h; dl[o] = l;
    }
}

// ---------------- elementwise / small kernels ----------------
__global__ void build_xm_kernel(const float* __restrict__ x, const float* __restrict__ meta,
                                const float* __restrict__ bq, const float* __restrict__ bk,
                                const float* __restrict__ bv) {
    size_t idx = (size_t)blockIdx.x * blockDim.x + threadIdx.x;
    if (idx < 3 * D) {
        int z = idx / D, c = idx % D;
        g_bqkv[idx] = (z == 0) ? bq[c] : (z == 1) ? bk[c] : bv[c];
    }
    if (idx >= BTD) return;
    int d = idx % D;
    int t = (idx / D) % T;
    int b = idx / ((size_t)D * T);
    float v = (t < M) ? meta[(size_t)t * D + d] : x[((size_t)b * S + (t - M)) * D + d];
    g_xm[idx] = v;
    bsplit(v, g_xm_h[idx], g_xm_l[idx]);
}

__global__ void wlr_kernel(const float* __restrict__ xm, const float* __restrict__ Wlr,
                           const float* __restrict__ blr, float* __restrict__ w) {
    int row = blockIdx.x * 8 + (threadIdx.x >> 5);
    int lane = threadIdx.x & 31;
    const float* xr = xm + (size_t)row * D;
    float s = 0.f;
    for (int d = lane; d < D; d += 32) s += xr[d] * Wlr[d];
#pragma unroll
    for (int off = 16; off > 0; off >>= 1) s += __shfl_xor_sync(0xffffffffu, s, off);
    if (lane == 0) {
        float z = s + blr[0];
        w[row] = (1.f / (1.f + __expf(-z))) * MAX_ALR;
    }
}

__global__ void colsum_kernel(const float* __restrict__ X, float* __restrict__ out, int rows) {
    int c = threadIdx.x;  // blockDim = 512 = D
    int r0 = blockIdx.x * 64;
    int r1 = min(r0 + 64, rows);
    float s = 0.f;
    for (int r = r0; r < r1; r++) s += X[(size_t)r * D + c];
    atomicAdd(&out[c], s);
}

__global__ void adamw_kernel(const float* __restrict__ p, const float* __restrict__ g,
                             float* __restrict__ out, int n) {
    int i = blockIdx.x * blockDim.x + threadIdx.x;
    if (i >= n) return;
    float gv = g[i];
    out[i] = p[i] * (1.f - LR * WD) - LR * gv / (fabsf(gv) + EPS);
}

// ---------------- sliding window attention (16 queries / block, 256 threads) ----------------
constexpr int QB = 16;
constexpr int KROWS = WIN + QB - 1;  // 143

__global__ __launch_bounds__(256) void attn_kernel2(const float* __restrict__ qkv) {
    __shared__ float Ksm[KROWS * 65];
    __shared__ float Qsm[QB * 64];
    __shared__ float sc[QB * 128];
    __shared__ float invs[QB];

    const float* qs = qkv;
    const float* ks = qkv + BTD;
    const float* vs = qkv + 2 * BTD;

    const int i0 = M + blockIdx.x * QB;
    const int h = blockIdx.y;
    const int b = blockIdx.z;
    const int tid = threadIdx.x;
    const int lane = tid & 31, w = tid >> 5;

    const int jlo = max(0, i0 - (WIN - 1));
    const int nrows = (i0 + QB - 1) - jlo + 1;

    for (int idx = tid; idx < nrows * 64; idx += 256) {
        int r = idx >> 6, d = idx & 63;
        Ksm[r * 65 + d] = ks[((size_t)(b * T + jlo + r)) * D + h * HD + d];
    }
    for (int idx = tid; idx < QB * 64; idx += 256)
        Qsm[idx] = qs[((size_t)(b * T + i0 + (idx >> 6))) * D + h * HD + (idx & 63)];
    __syncthreads();

    {
        const int slot = tid & 127;
        const int qoff = tid >> 7;
#pragma unroll
        for (int step = 0; step < QB / 2; step++) {
            int q = step * 2 + qoff;
            int j = (i0 + q) - (WIN - 1) + slot;
            float s = -1e30f;
            if (j >= 0) {
                int r = j - jlo;
                const float* kp = &Ksm[r * 65];
                const float* qp = &Qsm[q * 64];
                float acc = 0.f;
#pragma unroll
                for (int d = 0; d < HD; d++) acc += qp[d] * kp[d];
                s = acc * 0.125f;
            }
            sc[q * 128 + slot] = s;
        }
    }
    __syncthreads();

    for (int q = w; q < QB; q += 8) {
        float x0 = sc[q * 128 + lane];
        float x1 = sc[q * 128 + lane + 32];
        float x2 = sc[q * 128 + lane + 64];
        float x3 = sc[q * 128 + lane + 96];
        float mx = fmaxf(fmaxf(x0, x1), fmaxf(x2, x3));
#pragma unroll
        for (int off = 16; off > 0; off >>= 1) mx = fmaxf(mx, __shfl_xor_sync(0xffffffffu, mx, off));
        float e0 = __expf(x0 - mx), e1 = __expf(x1 - mx), e2 = __expf(x2 - mx), e3 = __expf(x3 - mx);
        sc[q * 128 + lane] = e0;
        sc[q * 128 + lane + 32] = e1;
        sc[q * 128 + lane + 64] = e2;
        sc[q * 128 + lane + 96] = e3;
        float sum = e0 + e1 + e2 + e3;
#pragma unroll
        for (int off = 16; off > 0; off >>= 1) sum += __shfl_xor_sync(0xffffffffu, sum, off);
        if (lane == 0) invs[q] = 1.f / sum;
    }
    __syncthreads();

    for (int idx = tid; idx < nrows * 64; idx += 256) {
        int r = idx >> 6, d = idx & 63;
        Ksm[r * 65 + d] = vs[((size_t)(b * T + jlo + r)) * D + h * HD + d];
    }
    __syncthreads();

    const int d = tid & 63, g = tid >> 6;
    float acc[4] = {0.f, 0.f, 0.f, 0.f};
    for (int r = 0; r < nrows; r++) {
        float vv = Ksm[r * 65 + d];
        int j = jlo + r;
#pragma unroll
        for (int qi = 0; qi < 4; qi++) {
            int q = g + qi * 4;
            int jj = j - (i0 + q) + (WIN - 1);
            if (jj >= 0 && jj < WIN) acc[qi] += sc[q * 128 + jj] * vv;
        }
    }
#pragma unroll
    for (int qi = 0; qi < 4; qi++) {
        int q = g + qi * 4;
        float ov = acc[qi] * invs[q];
        size_t off = ((size_t)(b * S + (i0 - M) + q)) * D + h * HD + d;
        bsplit(ov, g_o_h[off], g_o_l[off]);
    }
}

// ---------------- host-side launch ----------------
template <int EPI, int ZMODE>
static void launch_gemm(dim3 grid, cudaStream_t st, const bf16* Ah, const bf16* Al,
                        const bf16* Bh, const bf16* Bl, const float* bias, const float* R,
                        float* Cf, bf16* Ch, bf16* Cl, float* Zf,
                        const float* P1, const float* P2, float* O2,
                        int Md, int Nd, int Kd) {
    cudaFuncSetAttribute(gemm_bf16x3<EPI, ZMODE>,
                         cudaFuncAttributeMaxDynamicSharedMemorySize, GSMEM);
    gemm_bf16x3<EPI, ZMODE><<<grid, 256, GSMEM, st>>>(Ah, Al, Bh, Bl, bias, R, Cf, Ch, Cl,
                                                      Zf, P1, P2, O2, Md, Nd, Kd);
}

template <typename Tsym>
static void* symp(Tsym& s) {
    void* p = nullptr;
    cudaGetSymbolAddress(&p, s);
    return p;
}

extern "C" void kernel_launch(void* const* d_in, const int* in_sizes, int n_in,
                              void* d_out, int out_size) {
    const float* x     = (const float*)d_in[0];
    const float* meta  = (const float*)d_in[1];
    const float* lmm_W = (const float*)d_in[2];
    const float* lmm_b = (const float*)d_in[3];
    const float* Wq    = (const float*)d_in[4];
    const float* bq    = (const float*)d_in[5];
    const float* Wk    = (const float*)d_in[6];
    const float* bk    = (const float*)d_in[7];
    const float* Wv    = (const float*)d_in[8];
    const float* bv    = (const float*)d_in[9];
    const float* W_lr  = (const float*)d_in[10];
    const float* b_lr  = (const float*)d_in[11];
    const float* swa_W = (const float*)d_in[12];
    const float* swa_b = (const float*)d_in[13];
    float* out = (float*)d_out;

    float *xm = (float*)symp(g_xm), *pj = (float*)symp(g_pj), *w = (float*)symp(g_w);
    float *z1 = (float*)symp(g_z1), *h1 = (float*)symp(g_h1);
    float *g2 = (float*)symp(g_g2);
    float *dz2 = (float*)symp(g_dz2), *dz1 = (float*)symp(g_dz1);
    float *gW = (float*)symp(g_gW), *gb = (float*)symp(g_gb);
    float *Wu = (float*)symp(g_Wu), *bu = (float*)symp(g_bu);
    float *r1 = (float*)symp(g_r1), *qkv = (float*)symp(g_qkv);
    float *part = (float*)symp(g_part), *part2 = (float*)symp(g_part2);
    float *bqkv = (float*)symp(g_bqkv);
    bf16 *xm_h = (bf16*)symp(g_xm_h), *xm_l = (bf16*)symp(g_xm_l);
    bf16 *pj_h = (bf16*)symp(g_pj_h), *pj_l = (bf16*)symp(g_pj_l);
    bf16 *h1_h = (bf16*)symp(g_h1_h), *h1_l = (bf16*)symp(g_h1_l);
    bf16 *dz2_h = (bf16*)symp(g_dz2_h), *dz2_l = (bf16*)symp(g_dz2_l);
    bf16 *r1_h = (bf16*)symp(g_r1_h), *r1_l = (bf16*)symp(g_r1_l);
    bf16 *r_h = (bf16*)symp(g_r_h), *r_l = (bf16*)symp(g_r_l);
    bf16 *o_h = (bf16*)symp(g_o_h), *o_l = (bf16*)symp(g_o_l);
    bf16 *kT_h = (bf16*)symp(g_kT_h), *kT_l = (bf16*)symp(g_kT_l);
    bf16 *h1T_h = (bf16*)symp(g_h1T_h), *h1T_l = (bf16*)symp(g_h1T_l);
    bf16 *dz2T_h = (bf16*)symp(g_dz2T_h), *dz2T_l = (bf16*)symp(g_dz2T_l);
    bf16 *dz1T_h = (bf16*)symp(g_dz1T_h), *dz1T_l = (bf16*)symp(g_dz1T_l);
    bf16 *wT_h = (bf16*)symp(g_wT_h), *wT_l = (bf16*)symp(g_wT_l);
    bf16 *w2o_h = (bf16*)symp(g_w2o_h), *w2o_l = (bf16*)symp(g_w2o_l);
    bf16 *wuT_h = (bf16*)symp(g_wuT_h), *wuT_l = (bf16*)symp(g_wuT_l);

    float *q = pj, *k = pj + BTD, *v = pj + 2 * BTD;
    bf16 *q_h = pj_h, *q_l = pj_l;
    bf16 *k_h = pj_h + BTD, *k_l = pj_l + BTD;

    static cudaStream_t s1 = nullptr, s2 = nullptr;
    static cudaEvent_t evRoot, evA, evWlr, evK, evKT, evH1, evH1T, evG, evW2, evWS;
    if (!s1) {
        cudaStreamCreateWithFlags(&s1, cudaStreamNonBlocking);
        cudaStreamCreateWithFlags(&s2, cudaStreamNonBlocking);
        cudaEventCreateWithFlags(&evRoot, cudaEventDisableTiming);
        cudaEventCreateWithFlags(&evA, cudaEventDisableTiming);
        cudaEventCreateWithFlags(&evWlr, cudaEventDisableTiming);
        cudaEventCreateWithFlags(&evK, cudaEventDisableTiming);
        cudaEventCreateWithFlags(&evKT, cudaEventDisableTiming);
        cudaEventCreateWithFlags(&evH1, cudaEventDisableTiming);
        cudaEventCreateWithFlags(&evH1T, cudaEventDisableTiming);
        cudaEventCreateWithFlags(&evG, cudaEventDisableTiming);
        cudaEventCreateWithFlags(&evW2, cudaEventDisableTiming);
        cudaEventCreateWithFlags(&evWS, cudaEventDisableTiming);
    }

    const int EW_BLK = 256;
    const int ew_grid = (int)((BTD + EW_BLK - 1) / EW_BLK);
    const dim3 gBT(D / 128, BT / 64);           // (4, 68)
    const dim3 gQKV(D / 128, BT / 64, 3);
    const dim3 gSWA(D / 128, BT / 64, 3);
    const dim3 gTN(D / 128, D / 64, SPLK);      // (4, 8, 8)
    const dim3 gOUT(D / 128, BS_ / 64);         // (4, 64)
    const dim3 tBlk(32, 8);
    const dim3 gActT(D / 32, BT / 32);

    cudaEventRecord(evRoot, 0);

    // s2: SWA weights + W2-original split (slots 5..9)
    cudaStreamWaitEvent(s2, evRoot, 0);
    wsplitT_kernel<<<dim3(16, 16, 5), tBlk, 0, s2>>>(Wq, Wk, Wv, lmm_W, lmm_W + DD, swa_W, 5);
    cudaEventRecord(evWS, s2);

    // stream 0: critical-path weights (slots 0..4) + xm build
    wsplitT_kernel<<<dim3(16, 16, 5), tBlk>>>(Wq, Wk, Wv, lmm_W, lmm_W + DD, swa_W, 0);
    build_xm_kernel<<<ew_grid, EW_BLK>>>(x, meta, bq, bk, bv);
    cudaEventRecord(evA, 0);

    // s1: adaptive lr (parallel with QKV GEMM)
    cudaStreamWaitEvent(s1, evA, 0);
    wlr_kernel<<<BT / 8, 256, 0, s1>>>(xm, W_lr, b_lr, w);
    cudaEventRecord(evWlr, s1);

    // fused q/k/v projection
    launch_gemm<EPI_BIAS, 2>(gQKV, 0, xm_h, xm_l, wT_h + 0 * DD, wT_l + 0 * DD, bqkv,
                             nullptr, pj, pj_h, pj_l, nullptr, nullptr, nullptr, nullptr,
                             BT, D, D);
    cudaEventRecord(evK, 0);

    // s1: kT transpose (parallel with lmm forward)
    cudaStreamWaitEvent(s1, evK, 0);
    actT_kernel<<<gActT, tBlk, 0, s1>>>(k, kT_h, kT_l);
    cudaEventRecord(evKT, s1);

    // lmm1 (k -> h1, save z1)
    launch_gemm<EPI_RESSILU, 0>(gBT, 0, k_h, k_l, wT_h + 3 * DD, wT_l + 3 * DD, lmm_b, k,
                                h1, h1_h, h1_l, z1, nullptr, nullptr, nullptr, BT, D, D);
    cudaEventRecord(evH1, 0);

    // s2: h1T transpose (parallel with lmm2)
    cudaStreamWaitEvent(s2, evH1, 0);
    actT_kernel<<<gActT, tBlk, 0, s2>>>(h1, h1T_h, h1T_l);
    cudaEventRecord(evH1T, s2);

    // lmm2 fused with grad_out: outputs dz2 (f32 + bf16) and g2; needs w, v
    cudaStreamWaitEvent(0, evWlr, 0);
    cudaMemsetAsync(gb, 0, 2 * D * sizeof(float), 0);
    launch_gemm<EPI_GRADOUT, 0>(gBT, 0, h1_h, h1_l, wT_h + 4 * DD, wT_l + 4 * DD, lmm_b + D,
                                h1, dz2, dz2_h, dz2_l, nullptr, v, w, g2, BT, D, D);
    cudaEventRecord(evG, 0);

    // s1: gW2 branch (parallel with dh1 chain)
    cudaStreamWaitEvent(s1, evG, 0);
    actT_kernel<<<gActT, tBlk, 0, s1>>>(dz2, dz2T_h, dz2T_l);
    cudaStreamWaitEvent(s1, evH1T, 0);
    launch_gemm<EPI_NONE, 1>(gTN, s1, h1T_h, h1T_l, dz2T_h, dz2T_l, nullptr, nullptr,
                             part2, nullptr, nullptr, nullptr, nullptr, nullptr, nullptr,
                             D, D, BT);
    reduce_part_kernel<<<(DD + 255) / 256, 256, 0, s1>>>(part2, gW + DD, DD);
    colsum_kernel<<<(BT + 63) / 64, D, 0, s1>>>(dz2, gb + D, BT);
    cudaEventRecord(evW2, s1);

    // s0: dh1 GEMM fused with dz1; then gW1 chain (needs w2o from s2 split)
    cudaStreamWaitEvent(0, evWS, 0);
    launch_gemm<EPI_DZ1, 0>(gBT, 0, dz2_h, dz2_l, w2o_h, w2o_l, nullptr, nullptr,
                            dz1, nullptr, nullptr, nullptr, g2, z1, nullptr, BT, D, D);
    actT_kernel<<<gActT, tBlk>>>(dz1, dz1T_h, dz1T_l);
    cudaStreamWaitEvent(0, evKT, 0);
    launch_gemm<EPI_NONE, 1>(gTN, 0, kT_h, kT_l, dz1T_h, dz1T_l, nullptr, nullptr,
                             part, nullptr, nullptr, nullptr, nullptr, nullptr, nullptr,
                             D, D, BT);
    reduce_part_kernel<<<(DD + 255) / 256, 256>>>(part, gW, DD);
    colsum_kernel<<<(BT + 63) / 64, D>>>(dz1, gb, BT);

    cudaStreamWaitEvent(0, evW2, 0);
    adamw_kernel<<<(2 * DD + 255) / 256, 256>>>(lmm_W, gW, Wu, 2 * DD);
    adamw_kernel<<<(2 * D + 255) / 256, 256>>>(lmm_b, gb, bu, 2 * D);
    wuT_kernel<<<dim3(16, 16, 2), tBlk>>>(Wu);

    launch_gemm<EPI_RESSILU, 0>(gBT, 0, q_h, q_l, wuT_h, wuT_l, bu, q,
                                r1, r1_h, r1_l, nullptr, nullptr, nullptr, nullptr, BT, D, D);
    launch_gemm<EPI_RESSILU, 0>(gBT, 0, r1_h, r1_l, wuT_h + DD, wuT_l + DD, bu + D, r1,
                                nullptr, r_h, r_l, nullptr, nullptr, nullptr, nullptr,
                                BT, D, D);

    launch_gemm<EPI_BIAS, 2>(gSWA, 0, r_h, r_l, wT_h + 5 * DD, wT_l + 5 * DD, swa_b,
                             nullptr, qkv, nullptr, nullptr, nullptr, nullptr, nullptr,
                             nullptr, BT, D, D);

    {
        dim3 grid(S / QB, H, B);
        attn_kernel2<<<grid, 256>>>(qkv);
    }

    launch_gemm<EPI_BIAS, 0>(gOUT, 0, o_h, o_l, wT_h + 8 * DD, wT_l + 8 * DD, swa_b + 3 * D,
                             nullptr, out, nullptr, nullptr, nullptr, nullptr, nullptr,
                             nullptr, BS_, D, D);
}

// round 16
// speedup vs baseline: 1.0370x; 1.0370x over previous
#include <cuda_runtime.h>
#include <cuda_bf16.h>
#include <math.h>
#include <stdint.h>

// ---------------- problem constants ----------------
constexpr int B = 4, S = 1024, D = 512, M = 64, H = 8, WIN = 128;
constexpr int T = M + S;            // 1088
constexpr int BT = B * T;           // 4352
constexpr int BS_ = B * S;          // 4096
constexpr int HD = D / H;           // 64
constexpr float LR = 1e-3f, WD = 1e-2f, MAX_ALR = 0.1f, EPS = 1e-8f;
constexpr size_t BTD = (size_t)BT * D;
constexpr size_t BSD = (size_t)BS_ * D;
constexpr int DD = D * D;
constexpr int SPLK = 8;             // 4352/8 = 544 = 17*32

typedef __nv_bfloat16 bf16;

// ---------------- scratch (static device globals; no allocation) ----------------
__device__ float g_xm[BTD];
__device__ float g_pj[3 * BTD];     // fused q,k,v f32
__device__ float g_w[BT];
__device__ float g_z1[BTD];
__device__ float g_h1[BTD];
__device__ float g_g2[BTD];
__device__ float g_dz2[BTD];
__device__ float g_dz1[BTD];
__device__ float g_gW[2 * DD];
__device__ float g_gb[2 * D];
__device__ float g_Wu[2 * DD];
__device__ float g_bu[2 * D];
__device__ float g_r1[BTD];
__device__ float g_qkv[3 * BTD];
__device__ float g_part[SPLK * DD];
__device__ float g_part2[SPLK * DD];
__device__ float g_bqkv[3 * D];
// bf16 hi/lo activations (row-major [rows][k])
__device__ bf16 g_xm_h[BTD], g_xm_l[BTD];
__device__ bf16 g_pj_h[3 * BTD], g_pj_l[3 * BTD];
__device__ bf16 g_h1_h[BTD], g_h1_l[BTD];
__device__ bf16 g_dz2_h[BTD], g_dz2_l[BTD];
__device__ bf16 g_r1_h[BTD], g_r1_l[BTD];
__device__ bf16 g_r_h[BTD], g_r_l[BTD];
__device__ bf16 g_o_h[BSD], g_o_l[BSD];
// bf16 transposed activations [D][BT]
__device__ bf16 g_kT_h[BTD], g_kT_l[BTD];
__device__ bf16 g_h1T_h[BTD], g_h1T_l[BTD];
__device__ bf16 g_dz2T_h[BTD], g_dz2T_l[BTD];
__device__ bf16 g_dz1T_h[BTD], g_dz1T_l[BTD];
// bf16 weights: transposed [out][in] slots 0..8 = Wq,Wk,Wv,W1,W2,swa0..3
__device__ bf16 g_wT_h[9 * DD], g_wT_l[9 * DD];
__device__ bf16 g_w2o_h[DD], g_w2o_l[DD];
__device__ bf16 g_wuT_h[2 * DD], g_wuT_l[2 * DD];

// ---------------- helpers ----------------
__device__ __forceinline__ void bsplit(float f, bf16& h, bf16& l) {
    h = __float2bfloat16(f);
    l = __float2bfloat16(f - __bfloat162float(h));
}

__device__ __forceinline__ void mma_bf16(float* d, const uint32_t* a, const uint32_t* b) {
    asm volatile(
        "mma.sync.aligned.m16n8k16.row.col.f32.bf16.bf16.f32 "
        "{%0,%1,%2,%3}, {%4,%5,%6,%7}, {%8,%9}, {%0,%1,%2,%3};"
        : "+f"(d[0]), "+f"(d[1]), "+f"(d[2]), "+f"(d[3])
        : "r"(a[0]), "r"(a[1]), "r"(a[2]), "r"(a[3]), "r"(b[0]), "r"(b[1]));
}

__device__ __forceinline__ void ldsm_x4(uint32_t& r0, uint32_t& r1, uint32_t& r2,
                                        uint32_t& r3, uint32_t addr) {
    asm volatile("ldmatrix.sync.aligned.m8n8.x4.shared.b16 {%0,%1,%2,%3}, [%4];"
                 : "=r"(r0), "=r"(r1), "=r"(r2), "=r"(r3) : "r"(addr));
}

__device__ __forceinline__ void cp_async16(uint32_t sa, const void* gptr) {
    asm volatile("cp.async.cg.shared.global [%0], [%1], 16;" :: "r"(sa), "l"(gptr));
}
__device__ __forceinline__ void cp_commit() { asm volatile("cp.async.commit_group;"); }
template <int N>
__device__ __forceinline__ void cp_wait() { asm volatile("cp.async.wait_group %0;" :: "n"(N)); }

__device__ __forceinline__ float silu_grad(float z) {
    float sig = 1.f / (1.f + __expf(-z));
    return sig * (1.f + z * (1.f - sig));
}

// ---------------- bf16x3 GEMM, 64x128 tile, BK=32, 3-stage ----------------
// EPI: 0 bias; 1 none; 2 res+silu; 3 lmm2+grad_out fused; 4 dh1+dz1 fused
#define EPI_BIAS 0
#define EPI_NONE 1
#define EPI_RESSILU 2
#define EPI_GRADOUT 3
#define EPI_DZ1 4

constexpr int ROWB = 80;
constexpr int TILE_A = 64 * ROWB;
constexpr int TILE_Bt = 128 * ROWB;
constexpr int AOFF_L = TILE_A;
constexpr int BOFF_H = 2 * TILE_A;
constexpr int BOFF_L = 2 * TILE_A + TILE_Bt;
constexpr int STAGE_B = 2 * TILE_A + 2 * TILE_Bt;  // 30720 B
constexpr int NSTG = 3;
constexpr int GSMEM = NSTG * STAGE_B;              // 92160 B (2 CTAs/SM)

template <int EPI, int ZMODE>  // ZMODE: 0 none; 1 split-K z; 2 batched weights z
__global__ __launch_bounds__(256, 2) void gemm_bf16x3(
    const bf16* __restrict__ Ah, const bf16* __restrict__ Al,
    const bf16* __restrict__ Bh, const bf16* __restrict__ Bl,
    const float* __restrict__ bias, const float* __restrict__ R,
    float* __restrict__ Cf, bf16* __restrict__ Ch, bf16* __restrict__ Cl,
    float* __restrict__ Zf,
    const float* __restrict__ P1, const float* __restrict__ P2, float* __restrict__ O2,
    int Md, int Nd, int Kd) {
    extern __shared__ char smem[];
    const uint32_t sbase = (uint32_t)__cvta_generic_to_shared(smem);

    const int n0 = blockIdx.x * 128;
    const int m0 = blockIdx.y * 64;
    const int tid = threadIdx.x;
    const int warp = tid >> 5, lane = tid & 31;
    const int wm = warp >> 2, wn = warp & 3;
    const int gid = lane >> 2, tig = lane & 3;

    if (ZMODE == 2) {
        size_t wo = (size_t)blockIdx.z * Kd * Nd;
        size_t co = (size_t)blockIdx.z * Md * Nd;
        Bh += wo; Bl += wo;
        bias += (size_t)blockIdx.z * Nd;
        Cf += co;
        if (Ch) { Ch += co; Cl += co; }
    }
    int kbeg = 0, kend = Kd;
    if (ZMODE == 1) {
        int chunk = Kd / SPLK;
        kbeg = blockIdx.z * chunk;
        kend = kbeg + chunk;
        Cf += (size_t)blockIdx.z * Md * Nd;
    }
    const int nIter = (kend - kbeg) / 32;

    float acc[2][4][4];
#pragma unroll
    for (int i = 0; i < 2; i++)
#pragma unroll
        for (int j = 0; j < 4; j++)
#pragma unroll
            for (int c = 0; c < 4; c++) acc[i][j][c] = 0.f;

    uint32_t aterm[2], bterm[2];
#pragma unroll
    for (int im = 0; im < 2; im++)
        aterm[im] = (uint32_t)((wm * 32 + im * 16 + ((lane >> 3) & 1) * 8 + (lane & 7)) * ROWB
                               + ((lane >> 4) & 1) * 16);
#pragma unroll
    for (int p = 0; p < 2; p++)
        bterm[p] = (uint32_t)((wn * 32 + p * 16 + ((lane >> 4) & 1) * 8 + (lane & 7)) * ROWB
                               + ((lane >> 3) & 1) * 16);

    const int lrow = tid >> 2, lc = tid & 3;
    auto loadStage = [&](int k0, int st) {
        uint32_t s0 = sbase + st * STAGE_B;
        uint32_t da = s0 + lrow * ROWB + lc * 16;
        const size_t ga = (size_t)(m0 + lrow) * Kd + k0 + lc * 8;
        cp_async16(da, Ah + ga);
        cp_async16(da + AOFF_L, Al + ga);
        const size_t gb0 = (size_t)(n0 + lrow) * Kd + k0 + lc * 8;
        const size_t gb1 = (size_t)(n0 + lrow + 64) * Kd + k0 + lc * 8;
        uint32_t db0 = s0 + BOFF_H + lrow * ROWB + lc * 16;
        uint32_t db1 = db0 + 64 * ROWB;
        cp_async16(db0, Bh + gb0);
        cp_async16(db1, Bh + gb1);
        cp_async16(db0 + TILE_Bt, Bl + gb0);
        cp_async16(db1 + TILE_Bt, Bl + gb1);
        cp_commit();
    };

    loadStage(kbeg, 0);
    loadStage(kbeg + 32, 1);

    for (int it = 0; it < nIter; it++) {
        if (nIter - 1 - it >= 1) cp_wait<1>();
        else cp_wait<0>();
        __syncthreads();

        int wt = it + NSTG - 1;
        if (wt < nIter) loadStage(kbeg + wt * 32, wt % NSTG);

        const uint32_t so = sbase + (it % NSTG) * STAGE_B;

#pragma unroll
        for (int s = 0; s < 2; s++) {
            const uint32_t ks = s * 32;
            uint32_t ah[2][4], al[2][4];
#pragma unroll
            for (int im = 0; im < 2; im++) {
                ldsm_x4(ah[im][0], ah[im][1], ah[im][2], ah[im][3], so + aterm[im] + ks);
                ldsm_x4(al[im][0], al[im][1], al[im][2], al[im][3],
                        so + AOFF_L + aterm[im] + ks);
            }
            uint32_t bh[4][2], bl[4][2];
#pragma unroll
            for (int p = 0; p < 2; p++) {
                ldsm_x4(bh[2 * p][0], bh[2 * p][1], bh[2 * p + 1][0], bh[2 * p + 1][1],
                        so + BOFF_H + bterm[p] + ks);
                ldsm_x4(bl[2 * p][0], bl[2 * p][1], bl[2 * p + 1][0], bl[2 * p + 1][1],
                        so + BOFF_L + bterm[p] + ks);
            }
#pragma unroll
            for (int im = 0; im < 2; im++)
#pragma unroll
                for (int jn = 0; jn < 4; jn++) {
                    mma_bf16(acc[im][jn], ah[im], bh[jn]);
                    mma_bf16(acc[im][jn], ah[im], bl[jn]);
                    mma_bf16(acc[im][jn], al[im], bh[jn]);
                }
        }
    }

    // ---- epilogue ----
#pragma unroll
    for (int im = 0; im < 2; im++) {
#pragma unroll
        for (int jn = 0; jn < 4; jn++) {
            int col = n0 + wn * 32 + jn * 8 + tig * 2;
#pragma unroll
            for (int rr = 0; rr < 2; rr++) {
                int r_ = m0 + wm * 32 + im * 16 + gid + rr * 8;
                float v0 = acc[im][jn][rr * 2 + 0];
                float v1 = acc[im][jn][rr * 2 + 1];
                if (EPI == EPI_BIAS || EPI == EPI_RESSILU || EPI == EPI_GRADOUT) {
                    v0 += bias[col];
                    v1 += bias[col + 1];
                }
                size_t off = (size_t)r_ * Nd + col;
                if (EPI == EPI_RESSILU) {
                    if (Zf) { Zf[off] = v0; Zf[off + 1] = v1; }
                    float s0 = 1.f / (1.f + __expf(-v0));
                    float s1 = 1.f / (1.f + __expf(-v1));
                    v0 = R[off] + v0 * s0;
                    v1 = R[off + 1] + v1 * s1;
                } else if (EPI == EPI_GRADOUT) {
                    float s0 = 1.f / (1.f + __expf(-v0));
                    float s1 = 1.f / (1.f + __expf(-v1));
                    float p0 = R[off] + v0 * s0;
                    float p1 = R[off + 1] + v1 * s1;
                    float wr = P2[r_] * (2.0f / (float)D);
                    float ga0 = wr * (p0 - P1[off]);
                    float ga1 = wr * (p1 - P1[off + 1]);
                    O2[off] = ga0;
                    O2[off + 1] = ga1;
                    v0 = ga0 * silu_grad(v0);
                    v1 = ga1 * silu_grad(v1);
                } else if (EPI == EPI_DZ1) {
                    v0 = (P1[off] + v0) * silu_grad(P2[off]);
                    v1 = (P1[off + 1] + v1) * silu_grad(P2[off + 1]);
                }
                if (Cf) { Cf[off] = v0; Cf[off + 1] = v1; }
                if (Ch) {
                    bf16 h0, l0, h1, l1;
                    bsplit(v0, h0, l0);
                    bsplit(v1, h1, l1);
                    Ch[off] = h0; Ch[off + 1] = h1;
                    Cl[off] = l0; Cl[off + 1] = l1;
                }
            }
        }
    }
}

// ---------------- split-K reduce ----------------
__global__ void reduce_part_kernel(const float* __restrict__ part, float* __restrict__ out, int n) {
    int i = blockIdx.x * 256 + threadIdx.x;
    if (i >= n) return;
    float s = 0.f;
#pragma unroll
    for (int z = 0; z < SPLK; z++) s += part[(size_t)z * n + i];
    out[i] = s;
}

// ---------------- weight split (transposed + W2 original), z = zbase + blockIdx.z ----------------
__global__ void wsplitT_kernel(const float* __restrict__ Wq, const float* __restrict__ Wk,
                               const float* __restrict__ Wv, const float* __restrict__ W1,
                               const float* __restrict__ W2, const float* __restrict__ swa,
                               int zbase) {
    __shared__ float t[32][33];
    int z = zbase + blockIdx.z;
    const float* src = (z == 0) ? Wq : (z == 1) ? Wk : (z == 2) ? Wv : (z == 3) ? W1
                     : (z == 4 || z == 9) ? W2 : swa + (size_t)(z - 5) * DD;
    int c0 = blockIdx.x * 32, r0 = blockIdx.y * 32;
    int tx = threadIdx.x, ty = threadIdx.y;
#pragma unroll
    for (int kk = 0; kk < 4; kk++)
        t[ty + 8 * kk][tx] = src[(size_t)(r0 + ty + 8 * kk) * D + c0 + tx];
    __syncthreads();
    if (z < 9) {
        bf16* dh = g_wT_h + (size_t)z * DD;
        bf16* dl = g_wT_l + (size_t)z * DD;
#pragma unroll
        for (int kk = 0; kk < 4; kk++) {
            float v = t[tx][ty + 8 * kk];
            bf16 h, l;
            bsplit(v, h, l);
            size_t o = (size_t)(c0 + ty + 8 * kk) * D + r0 + tx;
            dh[o] = h; dl[o] = l;
        }
    } else {
#pragma unroll
        for (int kk = 0; kk < 4; kk++) {
            float v = t[ty + 8 * kk][tx];
            bf16 h, l;
            bsplit(v, h, l);
            size_t o = (size_t)(r0 + ty + 8 * kk) * D + c0 + tx;
            g_w2o_h[o] = h; g_w2o_l[o] = l;
        }
    }
}

__global__ void wuT_kernel(const float* __restrict__ Wu) {
    __shared__ float t[32][33];
    int z = blockIdx.z;
    const float* src = Wu + (size_t)z * DD;
    bf16* dh = g_wuT_h + (size_t)z * DD;
    bf16* dl = g_wuT_l + (size_t)z * DD;
    int c0 = blockIdx.x * 32, r0 = blockIdx.y * 32;
    int tx = threadIdx.x, ty = threadIdx.y;
#pragma unroll
    for (int kk = 0; kk < 4; kk++)
        t[ty + 8 * kk][tx] = src[(size_t)(r0 + ty + 8 * kk) * D + c0 + tx];
    __syncthreads();
#pragma unroll
    for (int kk = 0; kk < 4; kk++) {
        float v = t[tx][ty + 8 * kk];
        bf16 h, l;
        bsplit(v, h, l);
        size_t o = (size_t)(c0 + ty + 8 * kk) * D + r0 + tx;
        dh[o] = h; dl[o] = l;
    }
}

// activation transpose-split: src f32 [BT][D] -> dst bf16 hi/lo [D][BT]
__global__ void actT_kernel(const float* __restrict__ src, bf16* __restrict__ dh,
                            bf16* __restrict__ dl) {
    __shared__ float t[32][33];
    int c0 = blockIdx.x * 32;
    int r0 = blockIdx.y * 32;
    int tx = threadIdx.x, ty = threadIdx.y;
#pragma unroll
    for (int kk = 0; kk < 4; kk++)
        t[ty + 8 * kk][tx] = src[(size_t)(r0 + ty + 8 * kk) * D + c0 + tx];
    __syncthreads();
#pragma unroll
    for (int kk = 0; kk < 4; kk++) {
        float v = t[tx][ty + 8 * kk];
        bf16 h, l;
        bsplit(v, h, l);
        size_t o = (size_t)(c0 + ty + 8 * kk) * BT + r0 + tx;
        dh[o] = h; dl[o] = l;
    }
}

// ---------------- elementwise / small kernels ----------------
__global__ void build_xm_kernel(const float* __restrict__ x, const float* __restrict__ meta,
                                const float* __restrict__ bq, const float* __restrict__ bk,
                                const float* __restrict__ bv) {
    size_t idx = (size_t)blockIdx.x * blockDim.x + threadIdx.x;
    if (idx < 3 * D) {
        int z = idx / D, c = idx % D;
        g_bqkv[idx] = (z == 0) ? bq[c] : (z == 1) ? bk[c] : bv[c];
    }
    if (idx >= BTD) return;
    int d = idx % D;
    int t = (idx / D) % T;
    int b = idx / ((size_t)D * T);
    float v = (t < M) ? meta[(size_t)t * D + d] : x[((size_t)b * S + (t - M)) * D + d];
    g_xm[idx] = v;
    bsplit(v, g_xm_h[idx], g_xm_l[idx]);
}

__global__ void wlr_kernel(const float* __restrict__ xm, const float* __restrict__ Wlr,
                           const float* __restrict__ blr, float* __restrict__ w) {
    int row = blockIdx.x * 8 + (threadIdx.x >> 5);
    int lane = threadIdx.x & 31;
    const float* xr = xm + (size_t)row * D;
    float s = 0.f;
    for (int d = lane; d < D; d += 32) s += xr[d] * Wlr[d];
#pragma unroll
    for (int off = 16; off > 0; off >>= 1) s += __shfl_xor_sync(0xffffffffu, s, off);
    if (lane == 0) {
        float z = s + blr[0];
        w[row] = (1.f / (1.f + __expf(-z))) * MAX_ALR;
    }
}

__global__ void colsum_kernel(const float* __restrict__ X, float* __restrict__ out, int rows) {
    int c = threadIdx.x;  // blockDim = 512 = D
    int r0 = blockIdx.x * 64;
    int r1 = min(r0 + 64, rows);
    float s = 0.f;
    for (int r = r0; r < r1; r++) s += X[(size_t)r * D + c];
    atomicAdd(&out[c], s);
}

__global__ void adamw_kernel(const float* __restrict__ p, const float* __restrict__ g,
                             float* __restrict__ out, int n) {
    int i = blockIdx.x * blockDim.x + threadIdx.x;
    if (i >= n) return;
    float gv = g[i];
    out[i] = p[i] * (1.f - LR * WD) - LR * gv / (fabsf(gv) + EPS);
}

// ---------------- sliding window attention (16 queries / block, 256 threads) ----------------
constexpr int QB = 16;
constexpr int KROWS = WIN + QB - 1;  // 143

__global__ __launch_bounds__(256) void attn_kernel2(const float* __restrict__ qkv) {
    __shared__ float Ksm[KROWS * 65];
    __shared__ float Qsm[QB * 64];
    __shared__ float sc[QB * 128];
    __shared__ float invs[QB];

    const float* qs = qkv;
    const float* ks = qkv + BTD;
    const float* vs = qkv + 2 * BTD;

    const int i0 = M + blockIdx.x * QB;
    const int h = blockIdx.y;
    const int b = blockIdx.z;
    const int tid = threadIdx.x;
    const int lane = tid & 31, w = tid >> 5;

    const int jlo = max(0, i0 - (WIN - 1));
    const int nrows = (i0 + QB - 1) - jlo + 1;

    for (int idx = tid; idx < nrows * 64; idx += 256) {
        int r = idx >> 6, d = idx & 63;
        Ksm[r * 65 + d] = ks[((size_t)(b * T + jlo + r)) * D + h * HD + d];
    }
    for (int idx = tid; idx < QB * 64; idx += 256)
        Qsm[idx] = qs[((size_t)(b * T + i0 + (idx >> 6))) * D + h * HD + (idx & 63)];
    __syncthreads();

    {
        const int slot = tid & 127;
        const int qoff = tid >> 7;
#pragma unroll
        for (int step = 0; step < QB / 2; step++) {
            int q = step * 2 + qoff;
            int j = (i0 + q) - (WIN - 1) + slot;
            float s = -1e30f;
            if (j >= 0) {
                int r = j - jlo;
                const float* kp = &Ksm[r * 65];
                const float* qp = &Qsm[q * 64];
                float acc = 0.f;
#pragma unroll
                for (int d = 0; d < HD; d++) acc += qp[d] * kp[d];
                s = acc * 0.125f;
            }
            sc[q * 128 + slot] = s;
        }
    }
    __syncthreads();

    for (int q = w; q < QB; q += 8) {
        float x0 = sc[q * 128 + lane];
        float x1 = sc[q * 128 + lane + 32];
        float x2 = sc[q * 128 + lane + 64];
        float x3 = sc[q * 128 + lane + 96];
        float mx = fmaxf(fmaxf(x0, x1), fmaxf(x2, x3));
#pragma unroll
        for (int off = 16; off > 0; off >>= 1) mx = fmaxf(mx, __shfl_xor_sync(0xffffffffu, mx, off));
        float e0 = __expf(x0 - mx), e1 = __expf(x1 - mx), e2 = __expf(x2 - mx), e3 = __expf(x3 - mx);
        sc[q * 128 + lane] = e0;
        sc[q * 128 + lane + 32] = e1;
        sc[q * 128 + lane + 64] = e2;
        sc[q * 128 + lane + 96] = e3;
        float sum = e0 + e1 + e2 + e3;
#pragma unroll
        for (int off = 16; off > 0; off >>= 1) sum += __shfl_xor_sync(0xffffffffu, sum, off);
        if (lane == 0) invs[q] = 1.f / sum;
    }
    __syncthreads();

    for (int idx = tid; idx < nrows * 64; idx += 256) {
        int r = idx >> 6, d = idx & 63;
        Ksm[r * 65 + d] = vs[((size_t)(b * T + jlo + r)) * D + h * HD + d];
    }
    __syncthreads();

    const int d = tid & 63, g = tid >> 6;
    float acc[4] = {0.f, 0.f, 0.f, 0.f};
    for (int r = 0; r < nrows; r++) {
        float vv = Ksm[r * 65 + d];
        int j = jlo + r;
#pragma unroll
        for (int qi = 0; qi < 4; qi++) {
            int q = g + qi * 4;
            int jj = j - (i0 + q) + (WIN - 1);
            if (jj >= 0 && jj < WIN) acc[qi] += sc[q * 128 + jj] * vv;
        }
    }
#pragma unroll
    for (int qi = 0; qi < 4; qi++) {
        int q = g + qi * 4;
        float ov = acc[qi] * invs[q];
        size_t off = ((size_t)(b * S + (i0 - M) + q)) * D + h * HD + d;
        bsplit(ov, g_o_h[off], g_o_l[off]);
    }
}

// ---------------- host-side launch ----------------
template <int EPI, int ZMODE>
static void launch_gemm(dim3 grid, cudaStream_t st, const bf16* Ah, const bf16* Al,
                        const bf16* Bh, const bf16* Bl, const float* bias, const float* R,
                        float* Cf, bf16* Ch, bf16* Cl, float* Zf,
                        const float* P1, const float* P2, float* O2,
                        int Md, int Nd, int Kd) {
    cudaFuncSetAttribute(gemm_bf16x3<EPI, ZMODE>,
                         cudaFuncAttributeMaxDynamicSharedMemorySize, GSMEM);
    gemm_bf16x3<EPI, ZMODE><<<grid, 256, GSMEM, st>>>(Ah, Al, Bh, Bl, bias, R, Cf, Ch, Cl,
                                                      Zf, P1, P2, O2, Md, Nd, Kd);
}

template <typename Tsym>
static void* symp(Tsym& s) {
    void* p = nullptr;
    cudaGetSymbolAddress(&p, s);
    return p;
}

extern "C" void kernel_launch(void* const* d_in, const int* in_sizes, int n_in,
                              void* d_out, int out_size) {
    const float* x     = (const float*)d_in[0];
    const float* meta  = (const float*)d_in[1];
    const float* lmm_W = (const float*)d_in[2];
    const float* lmm_b = (const float*)d_in[3];
    const float* Wq    = (const float*)d_in[4];
    const float* bq    = (const float*)d_in[5];
    const float* Wk    = (const float*)d_in[6];
    const float* bk    = (const float*)d_in[7];
    const float* Wv    = (const float*)d_in[8];
    const float* bv    = (const float*)d_in[9];
    const float* W_lr  = (const float*)d_in[10];
    const float* b_lr  = (const float*)d_in[11];
    const float* swa_W = (const float*)d_in[12];
    const float* swa_b = (const float*)d_in[13];
    float* out = (float*)d_out;

    float *xm = (float*)symp(g_xm), *pj = (float*)symp(g_pj), *w = (float*)symp(g_w);
    float *z1 = (float*)symp(g_z1), *h1 = (float*)symp(g_h1);
    float *g2 = (float*)symp(g_g2);
    float *dz2 = (float*)symp(g_dz2), *dz1 = (float*)symp(g_dz1);
    float *gW = (float*)symp(g_gW), *gb = (float*)symp(g_gb);
    float *Wu = (float*)symp(g_Wu), *bu = (float*)symp(g_bu);
    float *r1 = (float*)symp(g_r1), *qkv = (float*)symp(g_qkv);
    float *part = (float*)symp(g_part), *part2 = (float*)symp(g_part2);
    float *bqkv = (float*)symp(g_bqkv);
    bf16 *xm_h = (bf16*)symp(g_xm_h), *xm_l = (bf16*)symp(g_xm_l);
    bf16 *pj_h = (bf16*)symp(g_pj_h), *pj_l = (bf16*)symp(g_pj_l);
    bf16 *h1_h = (bf16*)symp(g_h1_h), *h1_l = (bf16*)symp(g_h1_l);
    bf16 *dz2_h = (bf16*)symp(g_dz2_h), *dz2_l = (bf16*)symp(g_dz2_l);
    bf16 *r1_h = (bf16*)symp(g_r1_h), *r1_l = (bf16*)symp(g_r1_l);
    bf16 *r_h = (bf16*)symp(g_r_h), *r_l = (bf16*)symp(g_r_l);
    bf16 *o_h = (bf16*)symp(g_o_h), *o_l = (bf16*)symp(g_o_l);
    bf16 *kT_h = (bf16*)symp(g_kT_h), *kT_l = (bf16*)symp(g_kT_l);
    bf16 *h1T_h = (bf16*)symp(g_h1T_h), *h1T_l = (bf16*)symp(g_h1T_l);
    bf16 *dz2T_h = (bf16*)symp(g_dz2T_h), *dz2T_l = (bf16*)symp(g_dz2T_l);
    bf16 *dz1T_h = (bf16*)symp(g_dz1T_h), *dz1T_l = (bf16*)symp(g_dz1T_l);
    bf16 *wT_h = (bf16*)symp(g_wT_h), *wT_l = (bf16*)symp(g_wT_l);
    bf16 *w2o_h = (bf16*)symp(g_w2o_h), *w2o_l = (bf16*)symp(g_w2o_l);
    bf16 *wuT_h = (bf16*)symp(g_wuT_h), *wuT_l = (bf16*)symp(g_wuT_l);

    float *q = pj, *k = pj + BTD, *v = pj + 2 * BTD;
    bf16 *q_h = pj_h, *q_l = pj_l;
    bf16 *k_h = pj_h + BTD, *k_l = pj_l + BTD;
    bf16 *v_h = pj_h + 2 * BTD, *v_l = pj_l + 2 * BTD;  // written but unused downstream

    static cudaStream_t s1 = nullptr, s2 = nullptr;
    static cudaEvent_t evRoot, evA, evWlr, evK, evKT, evH1, evH1T, evG, evW2, evWS, evV, evQ;
    if (!s1) {
        cudaStreamCreateWithFlags(&s1, cudaStreamNonBlocking);
        cudaStreamCreateWithFlags(&s2, cudaStreamNonBlocking);
        cudaEventCreateWithFlags(&evRoot, cudaEventDisableTiming);
        cudaEventCreateWithFlags(&evA, cudaEventDisableTiming);
        cudaEventCreateWithFlags(&evWlr, cudaEventDisableTiming);
        cudaEventCreateWithFlags(&evK, cudaEventDisableTiming);
        cudaEventCreateWithFlags(&evKT, cudaEventDisableTiming);
        cudaEventCreateWithFlags(&evH1, cudaEventDisableTiming);
        cudaEventCreateWithFlags(&evH1T, cudaEventDisableTiming);
        cudaEventCreateWithFlags(&evG, cudaEventDisableTiming);
        cudaEventCreateWithFlags(&evW2, cudaEventDisableTiming);
        cudaEventCreateWithFlags(&evWS, cudaEventDisableTiming);
        cudaEventCreateWithFlags(&evV, cudaEventDisableTiming);
        cudaEventCreateWithFlags(&evQ, cudaEventDisableTiming);
    }

    const int EW_BLK = 256;
    const int ew_grid = (int)((BTD + EW_BLK - 1) / EW_BLK);
    const dim3 gBT(D / 128, BT / 64);           // (4, 68)
    const dim3 gSWA(D / 128, BT / 64, 3);
    const dim3 gTN(D / 128, D / 64, SPLK);      // (4, 8, 8)
    const dim3 gOUT(D / 128, BS_ / 64);         // (4, 64)
    const dim3 tBlk(32, 8);
    const dim3 gActT(D / 32, BT / 32);

    cudaEventRecord(evRoot, 0);

    // s2: SWA weights + W2-original split (slots 5..9)
    cudaStreamWaitEvent(s2, evRoot, 0);
    wsplitT_kernel<<<dim3(16, 16, 5), tBlk, 0, s2>>>(Wq, Wk, Wv, lmm_W, lmm_W + DD, swa_W, 5);
    cudaEventRecord(evWS, s2);

    // stream 0: critical-path weights (slots 0..4) + xm build + gb clear
    wsplitT_kernel<<<dim3(16, 16, 5), tBlk>>>(Wq, Wk, Wv, lmm_W, lmm_W + DD, swa_W, 0);
    build_xm_kernel<<<ew_grid, EW_BLK>>>(x, meta, bq, bk, bv);
    cudaMemsetAsync(gb, 0, 2 * D * sizeof(float), 0);
    cudaEventRecord(evA, 0);

    // s1: wlr, then v-projection (needed by lmm2), then q-projection (needed at retrieval)
    cudaStreamWaitEvent(s1, evA, 0);
    wlr_kernel<<<BT / 8, 256, 0, s1>>>(xm, W_lr, b_lr, w);
    cudaEventRecord(evWlr, s1);
    launch_gemm<EPI_BIAS, 0>(gBT, s1, xm_h, xm_l, wT_h + 2 * DD, wT_l + 2 * DD, bqkv + 2 * D,
                             nullptr, v, v_h, v_l, nullptr, nullptr, nullptr, nullptr,
                             BT, D, D);
    cudaEventRecord(evV, s1);
    launch_gemm<EPI_BIAS, 0>(gBT, s1, xm_h, xm_l, wT_h + 0 * DD, wT_l + 0 * DD, bqkv,
                             nullptr, q, q_h, q_l, nullptr, nullptr, nullptr, nullptr,
                             BT, D, D);
    cudaEventRecord(evQ, s1);

    // stream 0: k-projection only (critical path)
    launch_gemm<EPI_BIAS, 0>(gBT, 0, xm_h, xm_l, wT_h + 1 * DD, wT_l + 1 * DD, bqkv + D,
                             nullptr, k, k_h, k_l, nullptr, nullptr, nullptr, nullptr,
                             BT, D, D);
    cudaEventRecord(evK, 0);

    // s2: kT transpose (parallel with lmm forward)
    cudaStreamWaitEvent(s2, evK, 0);
    actT_kernel<<<gActT, tBlk, 0, s2>>>(k, kT_h, kT_l);
    cudaEventRecord(evKT, s2);

    // lmm1 (k -> h1, save z1)
    launch_gemm<EPI_RESSILU, 0>(gBT, 0, k_h, k_l, wT_h + 3 * DD, wT_l + 3 * DD, lmm_b, k,
                                h1, h1_h, h1_l, z1, nullptr, nullptr, nullptr, BT, D, D);
    cudaEventRecord(evH1, 0);

    // s2: h1T transpose (parallel with lmm2)
    cudaStreamWaitEvent(s2, evH1, 0);
    actT_kernel<<<gActT, tBlk, 0, s2>>>(h1, h1T_h, h1T_l);
    cudaEventRecord(evH1T, s2);

    // lmm2 fused with grad_out (needs w from wlr and v from s1)
    cudaStreamWaitEvent(0, evWlr, 0);
    cudaStreamWaitEvent(0, evV, 0);
    launch_gemm<EPI_GRADOUT, 0>(gBT, 0, h1_h, h1_l, wT_h + 4 * DD, wT_l + 4 * DD, lmm_b + D,
                                h1, dz2, dz2_h, dz2_l, nullptr, v, w, g2, BT, D, D);
    cudaEventRecord(evG, 0);

    // s1: gW2 branch (parallel with dh1 chain)
    cudaStreamWaitEvent(s1, evG, 0);
    actT_kernel<<<gActT, tBlk, 0, s1>>>(dz2, dz2T_h, dz2T_l);
    cudaStreamWaitEvent(s1, evH1T, 0);
    launch_gemm<EPI_NONE, 1>(gTN, s1, h1T_h, h1T_l, dz2T_h, dz2T_l, nullptr, nullptr,
                             part2, nullptr, nullptr, nullptr, nullptr, nullptr, nullptr,
                             D, D, BT);
    reduce_part_kernel<<<(DD + 255) / 256, 256, 0, s1>>>(part2, gW + DD, DD);
    colsum_kernel<<<(BT + 63) / 64, D, 0, s1>>>(dz2, gb + D, BT);
    cudaEventRecord(evW2, s1);

    // s0: dh1 GEMM fused with dz1; then gW1 chain (needs w2o from s2 split)
    cudaStreamWaitEvent(0, evWS, 0);
    launch_gemm<EPI_DZ1, 0>(gBT, 0, dz2_h, dz2_l, w2o_h, w2o_l, nullptr, nullptr,
                            dz1, nullptr, nullptr, nullptr, g2, z1, nullptr, BT, D, D);
    actT_kernel<<<gActT, tBlk>>>(dz1, dz1T_h, dz1T_l);
    cudaStreamWaitEvent(0, evKT, 0);
    launch_gemm<EPI_NONE, 1>(gTN, 0, kT_h, kT_l, dz1T_h, dz1T_l, nullptr, nullptr,
                             part, nullptr, nullptr, nullptr, nullptr, nullptr, nullptr,
                             D, D, BT);
    reduce_part_kernel<<<(DD + 255) / 256, 256>>>(part, gW, DD);
    colsum_kernel<<<(BT + 63) / 64, D>>>(dz1, gb, BT);

    cudaStreamWaitEvent(0, evW2, 0);
    adamw_kernel<<<(2 * DD + 255) / 256, 256>>>(lmm_W, gW, Wu, 2 * DD);
    adamw_kernel<<<(2 * D + 255) / 256, 256>>>(lmm_b, gb, bu, 2 * D);
    wuT_kernel<<<dim3(16, 16, 2), tBlk>>>(Wu);

    // retrieval (needs q from s1)
    cudaStreamWaitEvent(0, evQ, 0);
    launch_gemm<EPI_RESSILU, 0>(gBT, 0, q_h, q_l, wuT_h, wuT_l, bu, q,
                                r1, r1_h, r1_l, nullptr, nullptr, nullptr, nullptr, BT, D, D);
    launch_gemm<EPI_RESSILU, 0>(gBT, 0, r1_h, r1_l, wuT_h + DD, wuT_l + DD, bu + D, r1,
                                nullptr, r_h, r_l, nullptr, nullptr, nullptr, nullptr,
                                BT, D, D);

    launch_gemm<EPI_BIAS, 2>(gSWA, 0, r_h, r_l, wT_h + 5 * DD, wT_l + 5 * DD, swa_b,
                             nullptr, qkv, nullptr, nullptr, nullptr, nullptr, nullptr,
                             nullptr, BT, D, D);

    {
        dim3 grid(S / QB, H, B);
        attn_kernel2<<<grid, 256>>>(qkv);
    }

    launch_gemm<EPI_BIAS, 0>(gOUT, 0, o_h, o_l, wT_h + 8 * DD, wT_l + 8 * DD, swa_b + 3 * D,
                             nullptr, out, nullptr, nullptr, nullptr, nullptr, nullptr,
                             nullptr, BS_, D, D);
}